// round 2
// baseline (speedup 1.0000x reference)
#include <cuda_runtime.h>

// AdderConv + BatchNorm2d (training stats) for x[8,32,28,28], W[64,32,3,3], pad=1.
// Split into:
//   A) conv partial kernel: 1024 balanced blocks, k-split x4 over input channels,
//      writes positive |diff| partial sums to scratch.
//   B) combine+stats: sums 4 partials, negates, writes out, per-(n,oc) sum/sumsq.
//   C) apply: computes per-channel scale/bias from stats, normalizes (float4).

__device__ float g_partial[4 * 8 * 64 * 784];   // [ks][n][oc][hw], 6.4MB
__device__ float g_psum[512];                   // per (n,oc)
__device__ float g_psumsq[512];

__device__ __forceinline__ unsigned long long add_f32x2(unsigned long long a,
                                                        unsigned long long b) {
    unsigned long long r;
    asm("add.rn.f32x2 %0, %1, %2;" : "=l"(r) : "l"(a), "l"(b));
    return r;
}

// Kernel A: grid (4 spatial tiles 14x14, 8 oc-groups of 8, 32 = n*4+ks), 224 threads.
// Each block: 8 input channels (ks*8..ks*8+7), 8 output channels, one 14x14 tile, one n.
__global__ __launch_bounds__(224) void adder_partial_kernel(
    const float* __restrict__ x, const float* __restrict__ W)
{
    __shared__ __align__(16) float xs[8 * 16 * 16];   // 8KB
    __shared__ __align__(16) float nws[72 * 8];       // 2.25KB, negated, k-major

    const int s   = blockIdx.x;          // spatial tile 0..3
    const int ocg = blockIdx.y;          // 0..7
    const int zz  = blockIdx.z;          // 0..31
    const int ks  = zz & 3;              // k-split 0..3
    const int n   = zz >> 2;             // 0..7
    const int th  = (s >> 1) * 14;
    const int tw  = (s & 1) * 14;
    const int tid = threadIdx.x;
    const int c0  = ks * 8;

    // x tile: 8 channels, 16x16 halo'd
    const float* xb = x + n * (32 * 784) + c0 * 784;
    for (int i = tid; i < 8 * 256; i += 224) {
        int c = i >> 8, cell = i & 255;
        int r = cell >> 4, col = cell & 15;
        int gh = th - 1 + r, gw = tw - 1 + col;
        float v = 0.f;
        if ((unsigned)gh < 28u && (unsigned)gw < 28u)
            v = xb[c * 784 + gh * 28 + gw];
        xs[i] = v;
    }
    // negated W slice, k-major [72][8]
    const float* Wb = W + (ocg * 8) * 288 + c0 * 9;
    for (int i = tid; i < 8 * 72; i += 224) {
        int o = i & 7, lk = i >> 3;
        nws[lk * 8 + o] = -Wb[o * 288 + lk];
    }
    __syncthreads();

    if (tid < 196) {
        const int ph = tid / 14;
        const int pw = tid - ph * 14;
        unsigned long long acc0 = 0ull, acc1 = 0ull, acc2 = 0ull, acc3 = 0ull;
        const float* xp = xs + ph * 16 + pw;
        const ulonglong2* wp = (const ulonglong2*)nws;

        #pragma unroll 1
        for (int c = 0; c < 8; ++c) {
            const float* xc = xp + c * 256;
            #pragma unroll
            for (int r = 0; r < 3; ++r) {
                #pragma unroll
                for (int q = 0; q < 3; ++q) {
                    float xv = xc[r * 16 + q];
                    unsigned long long xx;
                    asm("mov.b64 %0, {%1, %1};" : "=l"(xx) : "r"(__float_as_uint(xv)));
                    const ulonglong2* w4 = wp + (c * 9 + r * 3 + q) * 2;
                    ulonglong2 wA = w4[0];
                    ulonglong2 wB = w4[1];
                    unsigned long long d0 = add_f32x2(xx, wA.x) & 0x7FFFFFFF7FFFFFFFULL;
                    unsigned long long d1 = add_f32x2(xx, wA.y) & 0x7FFFFFFF7FFFFFFFULL;
                    unsigned long long d2 = add_f32x2(xx, wB.x) & 0x7FFFFFFF7FFFFFFFULL;
                    unsigned long long d3 = add_f32x2(xx, wB.y) & 0x7FFFFFFF7FFFFFFFULL;
                    acc0 = add_f32x2(acc0, d0);
                    acc1 = add_f32x2(acc1, d1);
                    acc2 = add_f32x2(acc2, d2);
                    acc3 = add_f32x2(acc3, d3);
                }
            }
        }

        const int gh = th + ph, gw = tw + pw;
        const int hw = gh * 28 + gw;
        float* pb = g_partial + ((size_t)(ks * 8 + n) * 64 + ocg * 8) * 784 + hw;
        unsigned long long a[4] = {acc0, acc1, acc2, acc3};
        #pragma unroll
        for (int j = 0; j < 4; ++j) {
            pb[(2 * j) * 784]     = __uint_as_float((unsigned)(a[j] & 0xFFFFFFFFu));
            pb[(2 * j + 1) * 784] = __uint_as_float((unsigned)(a[j] >> 32));
        }
    }
}

// Kernel B: combine 4 partials -> out, plus per-(n,oc) sum/sumsq.
// grid 512 (= n*64+oc), 224 threads; threads 0..195 each own one float4 (784 = 196*4).
__global__ __launch_bounds__(224) void combine_stats_kernel(float* __restrict__ out)
{
    const int bid = blockIdx.x;          // n*64 + oc
    const int tid = threadIdx.x;

    float s = 0.f, sq = 0.f;
    if (tid < 196) {
        const int off = tid * 4;
        float4 acc = make_float4(0.f, 0.f, 0.f, 0.f);
        #pragma unroll
        for (int ks = 0; ks < 4; ++ks) {
            const float4 p = *(const float4*)(g_partial + ((size_t)ks * 512 + bid) * 784 + off);
            acc.x += p.x; acc.y += p.y; acc.z += p.z; acc.w += p.w;
        }
        float4 v = make_float4(-acc.x, -acc.y, -acc.z, -acc.w);
        *(float4*)(out + (size_t)bid * 784 + off) = v;
        s  = v.x + v.y + v.z + v.w;
        sq = v.x * v.x + v.y * v.y + v.z * v.z + v.w * v.w;
    }

    __shared__ float rs[256], rq[256];
    rs[tid] = s; rq[tid] = sq;
    if (tid < 32) { rs[224 + tid] = 0.f; rq[224 + tid] = 0.f; }
    __syncthreads();
    #pragma unroll
    for (int st = 128; st > 0; st >>= 1) {
        if (tid < st) { rs[tid] += rs[tid + st]; rq[tid] += rq[tid + st]; }
        __syncthreads();
    }
    if (tid == 0) { g_psum[bid] = rs[0]; g_psumsq[bid] = rq[0]; }
}

// Kernel C: finish stats per channel, apply BN. grid 392 x 256, float4 per thread.
__global__ __launch_bounds__(256) void apply_kernel(
    float* __restrict__ out, const float* __restrict__ gamma, const float* __restrict__ beta)
{
    __shared__ float sc_s[64], bi_s[64];
    const int tid = threadIdx.x;
    if (tid < 64) {
        float s = 0.f, sq = 0.f;
        #pragma unroll
        for (int n = 0; n < 8; ++n) {
            s  += g_psum[n * 64 + tid];
            sq += g_psumsq[n * 64 + tid];
        }
        float mean = s * (1.f / 6272.f);
        float var  = sq * (1.f / 6272.f) - mean * mean;
        float sc = gamma[tid] * rsqrtf(var + 1e-5f);
        sc_s[tid] = sc;
        bi_s[tid] = beta[tid] - mean * sc;
    }
    __syncthreads();

    const int gidx = (blockIdx.x * 256 + tid) * 4;   // 392*256*4 = 401408
    const int oc = (gidx / 784) & 63;
    float4 v = *(float4*)(out + gidx);
    const float sc = sc_s[oc], bi = bi_s[oc];
    v.x = v.x * sc + bi;
    v.y = v.y * sc + bi;
    v.z = v.z * sc + bi;
    v.w = v.w * sc + bi;
    *(float4*)(out + gidx) = v;
}

extern "C" void kernel_launch(void* const* d_in, const int* in_sizes, int n_in,
                              void* d_out, int out_size) {
    const float* x     = (const float*)d_in[0];  // [8,32,28,28]
    const float* W     = (const float*)d_in[1];  // [64,32,3,3]
    const float* gamma = (const float*)d_in[2];  // [64]
    const float* beta  = (const float*)d_in[3];  // [64]
    float* out = (float*)d_out;                  // [8,64,28,28]

    dim3 gA(4, 8, 32);
    adder_partial_kernel<<<gA, 224>>>(x, W);
    combine_stats_kernel<<<512, 224>>>(out);
    apply_kernel<<<392, 256>>>(out, gamma, beta);
}

// round 3
// speedup vs baseline: 1.0730x; 1.0730x over previous
#include <cuda_runtime.h>

// AdderConv + BatchNorm2d (training stats): x[8,32,28,28], W[64,32,3,3], pad=1.
// out[n,o,h,w] = -sum_k |x - w|, then per-channel BN (biased var, eps=1e-5).
//
// Kernel 1 (conv): grid (4 spatial 14x14 tiles, 8 oc-groups, 8 batch) x 224 thr.
//   Full K=288 per block, x tile loaded in two 16-channel phases (16KB smem),
//   negated W pre-packed as f32x2 pairs (9KB smem). Packed add/abs/acc in one
//   asm block (4 SASS per oc-pair). Epilogue: per-block per-oc sum/sumsq via
//   deterministic smem tree -> g_psum/g_psumsq partials (32 per oc).
// Kernel 2 (apply): 392x256; each block folds the 64x32 partials into
//   scale/bias (redundant, deterministic, L2-hit) and normalizes out (float4).

__device__ float g_psum[64 * 32];     // [oc][partial], partial = n*4 + s
__device__ float g_psumsq[64 * 32];

__device__ __forceinline__ void adder2(unsigned long long& acc,
                                       unsigned long long xx,
                                       unsigned long long w,
                                       unsigned long long mask) {
    asm("{\n\t"
        ".reg .b64 t;\n\t"
        "add.rn.f32x2 t, %1, %2;\n\t"
        "and.b64 t, t, %3;\n\t"
        "add.rn.f32x2 %0, %0, t;\n\t"
        "}"
        : "+l"(acc) : "l"(xx), "l"(w), "l"(mask));
}

__global__ __launch_bounds__(224, 7) void adder_conv_kernel(
    const float* __restrict__ x, const float* __restrict__ W, float* __restrict__ out)
{
    __shared__ __align__(16) float xs[16 * 256];                  // 16KB, reused for reduce
    __shared__ __align__(16) unsigned long long nws[288 * 4];     // 9KB packed (-w) pairs

    const int s   = blockIdx.x;          // spatial tile 0..3 (14x14)
    const int ocg = blockIdx.y;          // 0..7
    const int n   = blockIdx.z;          // 0..7
    const int th  = (s >> 1) * 14;
    const int tw  = (s & 1) * 14;
    const int tid = threadIdx.x;

    // Pre-pack negated weights: nws[k*4+p] = pack(-W[2p][k], -W[2p+1][k])
    const float* Wb = W + (ocg * 8) * 288;
    for (int i = tid; i < 288 * 4; i += 224) {
        int k = i >> 2, p = i & 3;
        unsigned lo = __float_as_uint(-Wb[(2 * p) * 288 + k]);
        unsigned hi = __float_as_uint(-Wb[(2 * p + 1) * 288 + k]);
        nws[i] = ((unsigned long long)hi << 32) | lo;
    }

    const unsigned long long mask = 0x7FFFFFFF7FFFFFFFULL;
    unsigned long long acc0 = 0ull, acc1 = 0ull, acc2 = 0ull, acc3 = 0ull;
    const int ph = tid / 14;
    const int pw = tid - ph * 14;
    const float* xb = x + n * (32 * 784);

    for (int half = 0; half < 2; ++half) {
        __syncthreads();
        // Load 16-channel x tile with zero halo
        const float* xh = xb + half * 16 * 784;
        for (int i = tid; i < 16 * 256; i += 224) {
            int c = i >> 8, cell = i & 255;
            int r = cell >> 4, col = cell & 15;
            int gh = th - 1 + r, gw = tw - 1 + col;
            float v = 0.f;
            if ((unsigned)gh < 28u && (unsigned)gw < 28u)
                v = xh[c * 784 + gh * 28 + gw];
            xs[i] = v;
        }
        __syncthreads();

        if (tid < 196) {
            #pragma unroll 1
            for (int c = 0; c < 16; ++c) {
                const int xbase = c * 256 + ph * 16 + pw;
                const int kbase = (half * 16 + c) * 9;
                #pragma unroll
                for (int r = 0; r < 3; ++r) {
                    #pragma unroll
                    for (int q = 0; q < 3; ++q) {
                        float xv = xs[xbase + r * 16 + q];
                        unsigned long long xx;
                        asm("mov.b64 %0, {%1, %1};" : "=l"(xx) : "r"(__float_as_uint(xv)));
                        const ulonglong2* wp =
                            (const ulonglong2*)(nws + (kbase + r * 3 + q) * 4);
                        ulonglong2 wA = wp[0];
                        ulonglong2 wB = wp[1];
                        adder2(acc0, xx, wA.x, mask);
                        adder2(acc1, xx, wA.y, mask);
                        adder2(acc2, xx, wB.x, mask);
                        adder2(acc3, xx, wB.y, mask);
                    }
                }
            }
        }
    }
    __syncthreads();

    // Epilogue: write outputs, stage per-oc sum & sumsq into smem (reuse xs).
    float* red = xs;                      // 16 rows x 224: rows 0..7 sum, 8..15 sumsq
    if (tid < 196) {
        const int gh = th + ph, gw = tw + pw;
        const int hw = gh * 28 + gw;
        float* ob = out + ((size_t)(n * 64 + ocg * 8)) * 784 + hw;
        unsigned long long a[4] = {acc0, acc1, acc2, acc3};
        #pragma unroll
        for (int p = 0; p < 4; ++p) {
            float v0 = -__uint_as_float((unsigned)(a[p] & 0xFFFFFFFFu));
            float v1 = -__uint_as_float((unsigned)(a[p] >> 32));
            ob[(2 * p) * 784]     = v0;
            ob[(2 * p + 1) * 784] = v1;
            red[(2 * p) * 224 + tid]           = v0;
            red[(2 * p + 1) * 224 + tid]       = v1;
            red[(8 + 2 * p) * 224 + tid]       = v0 * v0;
            red[(8 + 2 * p + 1) * 224 + tid]   = v1 * v1;
        }
    } else {
        #pragma unroll
        for (int j = 0; j < 16; ++j) red[j * 224 + tid] = 0.f;
    }
    __syncthreads();

    // Deterministic tree: 224 -> 112 -> 56 -> 28 -> 14 -> 7, then 7-way serial.
    #pragma unroll
    for (int st = 112; st >= 7; st >>= 1) {
        if (tid < st) {
            #pragma unroll
            for (int j = 0; j < 16; ++j)
                red[j * 224 + tid] += red[j * 224 + tid + st];
        }
        __syncthreads();
    }
    if (tid < 16) {
        float t = red[tid * 224];
        #pragma unroll
        for (int u = 1; u < 7; ++u) t += red[tid * 224 + u];
        const int pidx = n * 4 + s;
        if (tid < 8) g_psum[(ocg * 8 + tid) * 32 + pidx] = t;
        else         g_psumsq[(ocg * 8 + (tid - 8)) * 32 + pidx] = t;
    }
}

// Kernel 2: fold partials -> per-channel scale/bias, normalize out (float4).
__global__ __launch_bounds__(256) void apply_kernel(
    float* __restrict__ out, const float* __restrict__ gamma, const float* __restrict__ beta)
{
    __shared__ float sc_s[64], bi_s[64];
    const int tid = threadIdx.x;
    if (tid < 64) {
        float sv = 0.f, qv = 0.f;
        #pragma unroll
        for (int p = 0; p < 32; ++p) {
            sv += g_psum[tid * 32 + p];
            qv += g_psumsq[tid * 32 + p];
        }
        float mean = sv * (1.f / 6272.f);
        float var  = qv * (1.f / 6272.f) - mean * mean;
        float sc = gamma[tid] * rsqrtf(var + 1e-5f);
        sc_s[tid] = sc;
        bi_s[tid] = beta[tid] - mean * sc;
    }
    __syncthreads();

    const int gidx = (blockIdx.x * 256 + tid) * 4;   // 392*256*4 = 401408
    const int oc = (gidx / 784) & 63;
    float4 v = *(float4*)(out + gidx);
    const float sc = sc_s[oc], bi = bi_s[oc];
    v.x = v.x * sc + bi;
    v.y = v.y * sc + bi;
    v.z = v.z * sc + bi;
    v.w = v.w * sc + bi;
    *(float4*)(out + gidx) = v;
}

extern "C" void kernel_launch(void* const* d_in, const int* in_sizes, int n_in,
                              void* d_out, int out_size) {
    const float* x     = (const float*)d_in[0];  // [8,32,28,28]
    const float* W     = (const float*)d_in[1];  // [64,32,3,3]
    const float* gamma = (const float*)d_in[2];  // [64]
    const float* beta  = (const float*)d_in[3];  // [64]
    float* out = (float*)d_out;                  // [8,64,28,28]

    dim3 g1(4, 8, 8);
    adder_conv_kernel<<<g1, 224>>>(x, W, out);
    apply_kernel<<<392, 256>>>(out, gamma, beta);
}

// round 4
// speedup vs baseline: 1.2797x; 1.1926x over previous
#include <cuda_runtime.h>

// AdderConv + BatchNorm2d (training stats): x[8,32,28,28], W[64,32,3,3], pad=1.
// out[n,o,h,w] = -sum_k |x - w|, then per-channel BN (biased var, eps=1e-5).
//
// Kernel 1 (conv): grid (4 tiles 14x14, 8 oc-groups of 8, 8 batch) x 256 thr.
//   x tile stored PRE-DUPLICATED as (x,x) 64-bit pairs, two 16-channel phases
//   (32KB). Negated W packed as f32x2 oc-pairs (9KB). Inner loop per k:
//   LDS.64 + 2x LDS.128 + 4x (FADD2, 2 LOP3, FADD2). Epilogue: per-block
//   per-oc sum/sumsq smem tree -> 2048 partials.
// Kernel 2 (stats): 1 block x 512 thr, folds partials -> g_scale/g_bias[64].
// Kernel 3 (apply): 392x256, float4 normalize using precomputed scale/bias.

__device__ float g_psum[64 * 32];     // [oc][partial], partial = n*4 + s
__device__ float g_psumsq[64 * 32];
__device__ float g_scale[64];
__device__ float g_bias[64];

__device__ __forceinline__ void adder2(unsigned long long& acc,
                                       unsigned long long xx,
                                       unsigned long long w,
                                       unsigned long long mask) {
    asm("{\n\t"
        ".reg .b64 t;\n\t"
        "add.rn.f32x2 t, %1, %2;\n\t"
        "and.b64 t, t, %3;\n\t"
        "add.rn.f32x2 %0, %0, t;\n\t"
        "}"
        : "+l"(acc) : "l"(xx), "l"(w), "l"(mask));
}

__global__ __launch_bounds__(256) void adder_conv_kernel(
    const float* __restrict__ x, const float* __restrict__ W, float* __restrict__ out)
{
    __shared__ __align__(16) unsigned long long xsd[16 * 256];   // 32KB, (x,x) pairs
    __shared__ __align__(16) unsigned long long nws[288 * 4];    // 9KB, (-w,-w') oc-pairs

    const int s   = blockIdx.x;          // spatial tile 0..3 (14x14)
    const int ocg = blockIdx.y;          // 0..7
    const int n   = blockIdx.z;          // 0..7
    const int th  = (s >> 1) * 14;
    const int tw  = (s & 1) * 14;
    const int tid = threadIdx.x;

    // nws[k*4+p] = pack(-W[2p][k], -W[2p+1][k])
    const float* Wb = W + (ocg * 8) * 288;
    for (int i = tid; i < 288 * 4; i += 256) {
        int k = i >> 2, p = i & 3;
        unsigned lo = __float_as_uint(-Wb[(2 * p) * 288 + k]);
        unsigned hi = __float_as_uint(-Wb[(2 * p + 1) * 288 + k]);
        nws[i] = ((unsigned long long)hi << 32) | lo;
    }

    const unsigned long long mask = 0x7FFFFFFF7FFFFFFFULL;
    unsigned long long acc0 = 0ull, acc1 = 0ull, acc2 = 0ull, acc3 = 0ull;
    const int ph = tid / 14;             // valid for tid < 196
    const int pw = tid - ph * 14;
    const float* xb = x + n * (32 * 784);

    for (int half = 0; half < 2; ++half) {
        __syncthreads();
        // 16-channel halo'd x tile, each value duplicated into a 64-bit pair
        const float* xh = xb + half * 16 * 784;
        for (int i = tid; i < 16 * 256; i += 256) {
            int c = i >> 8, cell = i & 255;
            int r = cell >> 4, col = cell & 15;
            int gh = th - 1 + r, gw = tw - 1 + col;
            float v = 0.f;
            if ((unsigned)gh < 28u && (unsigned)gw < 28u)
                v = xh[c * 784 + gh * 28 + gw];
            unsigned u = __float_as_uint(v);
            xsd[i] = ((unsigned long long)u << 32) | u;
        }
        __syncthreads();

        if (tid < 196) {
            #pragma unroll 1
            for (int c = 0; c < 16; ++c) {
                const unsigned long long* xc = xsd + c * 256 + ph * 16 + pw;
                const ulonglong2* wk =
                    (const ulonglong2*)(nws + (half * 16 + c) * 36);
                #pragma unroll
                for (int r = 0; r < 3; ++r) {
                    #pragma unroll
                    for (int q = 0; q < 3; ++q) {
                        unsigned long long xx = xc[r * 16 + q];
                        ulonglong2 wA = wk[(r * 3 + q) * 2];
                        ulonglong2 wB = wk[(r * 3 + q) * 2 + 1];
                        adder2(acc0, xx, wA.x, mask);
                        adder2(acc1, xx, wA.y, mask);
                        adder2(acc2, xx, wB.x, mask);
                        adder2(acc3, xx, wB.y, mask);
                    }
                }
            }
        }
    }
    __syncthreads();

    // Epilogue: write outputs; per-oc sum & sumsq via deterministic smem tree.
    float* red = (float*)xsd;            // 16 rows x 256 floats (16KB of 32KB)
    if (tid < 196) {
        const int gh = th + ph, gw = tw + pw;
        const int hw = gh * 28 + gw;
        float* ob = out + ((size_t)(n * 64 + ocg * 8)) * 784 + hw;
        unsigned long long a[4] = {acc0, acc1, acc2, acc3};
        #pragma unroll
        for (int p = 0; p < 4; ++p) {
            float v0 = -__uint_as_float((unsigned)(a[p] & 0xFFFFFFFFu));
            float v1 = -__uint_as_float((unsigned)(a[p] >> 32));
            ob[(2 * p) * 784]     = v0;
            ob[(2 * p + 1) * 784] = v1;
            red[(2 * p) * 256 + tid]         = v0;
            red[(2 * p + 1) * 256 + tid]     = v1;
            red[(8 + 2 * p) * 256 + tid]     = v0 * v0;
            red[(8 + 2 * p + 1) * 256 + tid] = v1 * v1;
        }
    } else {
        #pragma unroll
        for (int j = 0; j < 16; ++j) red[j * 256 + tid] = 0.f;
    }
    __syncthreads();

    #pragma unroll
    for (int st = 128; st > 0; st >>= 1) {
        if (tid < st) {
            #pragma unroll
            for (int j = 0; j < 16; ++j)
                red[j * 256 + tid] += red[j * 256 + tid + st];
        }
        __syncthreads();
    }
    if (tid < 16) {
        const int pidx = n * 4 + s;
        float t = red[tid * 256];
        if (tid < 8) g_psum[(ocg * 8 + tid) * 32 + pidx] = t;
        else         g_psumsq[(ocg * 8 + (tid - 8)) * 32 + pidx] = t;
    }
}

// Kernel 2: fold 2048 partials -> per-channel scale/bias. 1 block, 512 threads.
__global__ __launch_bounds__(512) void stats_kernel(
    const float* __restrict__ gamma, const float* __restrict__ beta)
{
    const int tid = threadIdx.x;
    const int oc = tid >> 3;
    const int j  = tid & 7;

    float s = g_psum[oc * 32 + j]     + g_psum[oc * 32 + j + 8]
            + g_psum[oc * 32 + j + 16] + g_psum[oc * 32 + j + 24];
    float q = g_psumsq[oc * 32 + j]     + g_psumsq[oc * 32 + j + 8]
            + g_psumsq[oc * 32 + j + 16] + g_psumsq[oc * 32 + j + 24];
    #pragma unroll
    for (int d = 4; d > 0; d >>= 1) {
        s += __shfl_down_sync(0xFFFFFFFFu, s, d, 8);
        q += __shfl_down_sync(0xFFFFFFFFu, q, d, 8);
    }
    if (j == 0) {
        float mean = s * (1.f / 6272.f);
        float var  = q * (1.f / 6272.f) - mean * mean;
        float sc = gamma[oc] * rsqrtf(var + 1e-5f);
        g_scale[oc] = sc;
        g_bias[oc]  = beta[oc] - mean * sc;
    }
}

// Kernel 3: normalize out with precomputed scale/bias. 392x256, float4.
__global__ __launch_bounds__(256) void apply_kernel(float* __restrict__ out)
{
    __shared__ float sc_s[64], bi_s[64];
    const int tid = threadIdx.x;
    if (tid < 64) {
        sc_s[tid] = g_scale[tid];
        bi_s[tid] = g_bias[tid];
    }
    __syncthreads();

    const int gidx = (blockIdx.x * 256 + tid) * 4;   // 392*256*4 = 401408
    const int oc = (gidx / 784) & 63;
    float4 v = *(float4*)(out + gidx);
    const float sc = sc_s[oc], bi = bi_s[oc];
    v.x = v.x * sc + bi;
    v.y = v.y * sc + bi;
    v.z = v.z * sc + bi;
    v.w = v.w * sc + bi;
    *(float4*)(out + gidx) = v;
}

extern "C" void kernel_launch(void* const* d_in, const int* in_sizes, int n_in,
                              void* d_out, int out_size) {
    const float* x     = (const float*)d_in[0];  // [8,32,28,28]
    const float* W     = (const float*)d_in[1];  // [64,32,3,3]
    const float* gamma = (const float*)d_in[2];  // [64]
    const float* beta  = (const float*)d_in[3];  // [64]
    float* out = (float*)d_out;                  // [8,64,28,28]

    dim3 g1(4, 8, 8);
    adder_conv_kernel<<<g1, 256>>>(x, W, out);
    stats_kernel<<<1, 512>>>(gamma, beta);
    apply_kernel<<<392, 256>>>(out);
}

// round 6
// speedup vs baseline: 1.3611x; 1.0637x over previous
#include <cuda_runtime.h>

// AdderConv + BatchNorm2d (training stats): x[8,32,28,28], W[64,32,3,3], pad=1.
// out[n,o,h,w] = -sum_k |x - w|, then per-channel BN (biased var, eps=1e-5).
//
// Kernel 1 (conv partials): grid (4 row-tiles of 7x28, 8 oc-groups, 8n x 4 k-splits)
//   = 1024 blocks x 224 threads (warp = one output row, 28 active lanes).
//   8 input channels per block; x tile stored pre-duplicated as (x,x) 64-bit
//   pairs (18KB), negated W packed as f32x2 oc-pairs (2.25KB). Inner loop per k:
//   LDS.64 + 2x LDS.128 + 4x (FADD2, 2 LOP3, FADD2). Positive partial sums ->
//   g_partial[ks][n*64+oc][hw].
// Kernel 2 (combine): 512 blocks; sum 4 partials (independent float4 loads),
//   negate -> out, tree-reduce per-(n,oc) sum/sumsq.
// Kernel 3 (stats): 64 threads, fold to per-channel scale/bias.
// Kernel 4 (apply): 392x256 float4 normalize.

__device__ float g_partial[4 * 512 * 784];   // [ks][n*64+oc][hw], 6.4MB
__device__ float g_psum[512];                // per (n,oc)
__device__ float g_psumsq[512];
__device__ float g_scale[64];
__device__ float g_bias[64];

__device__ __forceinline__ void adder2(unsigned long long& acc,
                                       unsigned long long xx,
                                       unsigned long long w,
                                       unsigned long long mask) {
    asm("{\n\t"
        ".reg .b64 t;\n\t"
        "add.rn.f32x2 t, %1, %2;\n\t"
        "and.b64 t, t, %3;\n\t"
        "add.rn.f32x2 %0, %0, t;\n\t"
        "}"
        : "+l"(acc) : "l"(xx), "l"(w), "l"(mask));
}

__global__ __launch_bounds__(224) void adder_partial_kernel(
    const float* __restrict__ x, const float* __restrict__ W)
{
    // x tile: 8 channels x 9 halo rows x 32 cols (cols 0..29 used), (x,x) pairs
    __shared__ __align__(16) unsigned long long xsd[8 * 9 * 32];   // 18KB
    __shared__ __align__(16) unsigned long long nws[72 * 4];       // 2.25KB

    const int rt  = blockIdx.x;          // row-tile 0..3 (rows rt*7 .. rt*7+6)
    const int ocg = blockIdx.y;          // 0..7
    const int zz  = blockIdx.z;          // 0..31
    const int ks  = zz & 3;
    const int n   = zz >> 2;
    const int tid = threadIdx.x;
    const int row = tid >> 5;            // 0..6 (warp id = output row in tile)
    const int col = tid & 31;            // 0..31, active if < 28

    // Negated W slice for this k-split, packed per oc-pair:
    // nws[lk*4+p] = pack(-W[2p][ks*72+lk], -W[2p+1][ks*72+lk])
    const float* Wb = W + (ocg * 8) * 288 + ks * 72;
    for (int i = tid; i < 72 * 4; i += 224) {
        int lk = i >> 2, p = i & 3;
        unsigned lo = __float_as_uint(-Wb[(2 * p) * 288 + lk]);
        unsigned hi = __float_as_uint(-Wb[(2 * p + 1) * 288 + lk]);
        nws[i] = ((unsigned long long)hi << 32) | lo;
    }
    // x tile with zero halo, duplicated into 64-bit pairs
    const float* xb = x + n * (32 * 784) + (ks * 8) * 784;
    for (int i = tid; i < 8 * 9 * 32; i += 224) {
        int c = i >> 8;                  // /288? careful: 9*32=288 -> c = i/288
        c = i / 288;
        int rem = i - c * 288;
        int r = rem >> 5, cc = rem & 31;
        int gh = rt * 7 - 1 + r, gw = cc - 1;
        float v = 0.f;
        if ((unsigned)gh < 28u && (unsigned)gw < 28u)
            v = xb[c * 784 + gh * 28 + gw];
        unsigned u = __float_as_uint(v);
        xsd[i] = ((unsigned long long)u << 32) | u;
    }
    __syncthreads();

    const unsigned long long mask = 0x7FFFFFFF7FFFFFFFULL;
    unsigned long long acc0 = 0ull, acc1 = 0ull, acc2 = 0ull, acc3 = 0ull;

    if (col < 28) {
        #pragma unroll 1
        for (int c = 0; c < 8; ++c) {
            const unsigned long long* xc = xsd + c * 288 + row * 32 + col;
            const ulonglong2* wk = (const ulonglong2*)(nws + c * 36);
            #pragma unroll
            for (int r = 0; r < 3; ++r) {
                #pragma unroll
                for (int q = 0; q < 3; ++q) {
                    unsigned long long xx = xc[r * 32 + q];
                    ulonglong2 wA = wk[(r * 3 + q) * 2];
                    ulonglong2 wB = wk[(r * 3 + q) * 2 + 1];
                    adder2(acc0, xx, wA.x, mask);
                    adder2(acc1, xx, wA.y, mask);
                    adder2(acc2, xx, wB.x, mask);
                    adder2(acc3, xx, wB.y, mask);
                }
            }
        }

        const int gh = rt * 7 + row;
        const int hw = gh * 28 + col;
        float* pb = g_partial + ((size_t)(ks * 512 + n * 64 + ocg * 8)) * 784 + hw;
        unsigned long long a[4] = {acc0, acc1, acc2, acc3};
        #pragma unroll
        for (int p = 0; p < 4; ++p) {
            pb[(2 * p) * 784]     = __uint_as_float((unsigned)(a[p] & 0xFFFFFFFFu));
            pb[(2 * p + 1) * 784] = __uint_as_float((unsigned)(a[p] >> 32));
        }
    }
}

// Kernel 2: combine 4 partials -> out, per-(n,oc) sum/sumsq.
// grid 512 (= n*64+oc) x 256; threads 0..195 each own one float4 (784 = 196*4).
__global__ __launch_bounds__(256) void combine_kernel(float* __restrict__ out)
{
    const int bid = blockIdx.x;
    const int tid = threadIdx.x;

    float s = 0.f, sq = 0.f;
    if (tid < 196) {
        const int off = tid * 4;
        const float* p0 = g_partial + ((size_t)(0 * 512 + bid)) * 784 + off;
        const float* p1 = g_partial + ((size_t)(1 * 512 + bid)) * 784 + off;
        const float* p2 = g_partial + ((size_t)(2 * 512 + bid)) * 784 + off;
        const float* p3 = g_partial + ((size_t)(3 * 512 + bid)) * 784 + off;
        float4 a = *(const float4*)p0;
        float4 b = *(const float4*)p1;
        float4 c = *(const float4*)p2;
        float4 d = *(const float4*)p3;
        float4 v;
        v.x = -(a.x + b.x + c.x + d.x);
        v.y = -(a.y + b.y + c.y + d.y);
        v.z = -(a.z + b.z + c.z + d.z);
        v.w = -(a.w + b.w + c.w + d.w);
        *(float4*)(out + (size_t)bid * 784 + off) = v;
        s  = v.x + v.y + v.z + v.w;
        sq = v.x * v.x + v.y * v.y + v.z * v.z + v.w * v.w;
    }

    __shared__ float rs[256], rq[256];
    rs[tid] = s; rq[tid] = sq;
    __syncthreads();
    #pragma unroll
    for (int st = 128; st > 0; st >>= 1) {
        if (tid < st) { rs[tid] += rs[tid + st]; rq[tid] += rq[tid + st]; }
        __syncthreads();
    }
    if (tid == 0) { g_psum[bid] = rs[0]; g_psumsq[bid] = rq[0]; }
}

// Kernel 3: fold per-(n,oc) partials -> per-channel scale/bias. 64 threads.
__global__ __launch_bounds__(64) void stats_kernel(
    const float* __restrict__ gamma, const float* __restrict__ beta)
{
    const int oc = threadIdx.x;
    float s = 0.f, q = 0.f;
    #pragma unroll
    for (int n = 0; n < 8; ++n) {
        s += g_psum[n * 64 + oc];
        q += g_psumsq[n * 64 + oc];
    }
    float mean = s * (1.f / 6272.f);
    float var  = q * (1.f / 6272.f) - mean * mean;
    float sc = gamma[oc] * rsqrtf(var + 1e-5f);
    g_scale[oc] = sc;
    g_bias[oc]  = beta[oc] - mean * sc;
}

// Kernel 4: normalize out. 392x256, float4 per thread.
__global__ __launch_bounds__(256) void apply_kernel(float* __restrict__ out)
{
    __shared__ float sc_s[64], bi_s[64];
    const int tid = threadIdx.x;
    if (tid < 64) {
        sc_s[tid] = g_scale[tid];
        bi_s[tid] = g_bias[tid];
    }
    __syncthreads();

    const int gidx = (blockIdx.x * 256 + tid) * 4;   // 392*256*4 = 401408
    const int oc = (gidx / 784) & 63;
    float4 v = *(float4*)(out + gidx);
    const float sc = sc_s[oc], bi = bi_s[oc];
    v.x = v.x * sc + bi;
    v.y = v.y * sc + bi;
    v.z = v.z * sc + bi;
    v.w = v.w * sc + bi;
    *(float4*)(out + gidx) = v;
}

extern "C" void kernel_launch(void* const* d_in, const int* in_sizes, int n_in,
                              void* d_out, int out_size) {
    const float* x     = (const float*)d_in[0];  // [8,32,28,28]
    const float* W     = (const float*)d_in[1];  // [64,32,3,3]
    const float* gamma = (const float*)d_in[2];  // [64]
    const float* beta  = (const float*)d_in[3];  // [64]
    float* out = (float*)d_out;                  // [8,64,28,28]

    dim3 g1(4, 8, 32);
    adder_partial_kernel<<<g1, 224>>>(x, W);
    combine_kernel<<<512, 256>>>(out);
    stats_kernel<<<1, 64>>>(gamma, beta);
    apply_kernel<<<392, 256>>>(out);
}

// round 7
// speedup vs baseline: 1.3868x; 1.0189x over previous
#include <cuda_runtime.h>

// AdderConv + BatchNorm2d (training stats): x[8,32,28,28], W[64,32,3,3], pad=1.
// out[n,o,h,w] = -sum_k |x - w|, then per-channel BN (biased var, eps=1e-5).
//
// Kernel 1 (conv partials): grid (4 row-tiles 7x28, 8 oc-groups, 8n x 4 ks)
//   = 1024 blocks x 224 threads (warp = one output row). 8 input channels per
//   block; x tile pre-duplicated as (x,x) 64-bit pairs (18KB smem), negated W
//   packed as f32x2 oc-pairs. Inner loop per k: LDS.64 + 2x LDS.128 +
//   4x (FADD2, LOP3, FADD2). Positive partials -> g_partial. Also resets the
//   tail barrier counter (block 0) so graph replays work.
// Kernel 2 (fused tail): 512 blocks x 256 thr. Combine 4 partials into
//   registers, block-reduce sum/sumsq -> g_psum/g_psumsq, software global
//   barrier (counter spin; all 512 blocks co-resident: 256 thr, ~3KB smem),
//   then per-channel scale/bias and in-register normalize -> single out write.

__device__ float g_partial[4 * 512 * 784];   // [ks][n*64+oc][hw], 6.4MB
__device__ float g_psum[512];                // per (n,oc)
__device__ float g_psumsq[512];
__device__ unsigned g_ctr;                   // tail barrier counter

__device__ __forceinline__ void adder2(unsigned long long& acc,
                                       unsigned long long xx,
                                       unsigned long long w,
                                       unsigned long long mask) {
    asm("{\n\t"
        ".reg .b64 t;\n\t"
        "add.rn.f32x2 t, %1, %2;\n\t"
        "and.b64 t, t, %3;\n\t"
        "add.rn.f32x2 %0, %0, t;\n\t"
        "}"
        : "+l"(acc) : "l"(xx), "l"(w), "l"(mask));
}

__global__ __launch_bounds__(224) void adder_partial_kernel(
    const float* __restrict__ x, const float* __restrict__ W)
{
    __shared__ __align__(16) unsigned long long xsd[8 * 9 * 32];   // 18KB
    __shared__ __align__(16) unsigned long long nws[72 * 4];       // 2.25KB

    const int rt  = blockIdx.x;          // row-tile 0..3 (rows rt*7 .. rt*7+6)
    const int ocg = blockIdx.y;          // 0..7
    const int zz  = blockIdx.z;          // 0..31
    const int ks  = zz & 3;
    const int n   = zz >> 2;
    const int tid = threadIdx.x;
    const int row = tid >> 5;            // warp id = output row in tile
    const int col = tid & 31;            // active if < 28

    if (tid == 0 && rt == 0 && ocg == 0 && zz == 0) g_ctr = 0;  // replay-safe reset

    // Negated W slice for this k-split, packed per oc-pair.
    const float* Wb = W + (ocg * 8) * 288 + ks * 72;
    for (int i = tid; i < 72 * 4; i += 224) {
        int lk = i >> 2, p = i & 3;
        unsigned lo = __float_as_uint(-Wb[(2 * p) * 288 + lk]);
        unsigned hi = __float_as_uint(-Wb[(2 * p + 1) * 288 + lk]);
        nws[i] = ((unsigned long long)hi << 32) | lo;
    }
    // x tile with zero halo, duplicated into (x,x) 64-bit pairs.
    const float* xb = x + n * (32 * 784) + (ks * 8) * 784;
    for (int i = tid; i < 8 * 9 * 32; i += 224) {
        int c = i / 288;
        int rem = i - c * 288;
        int r = rem >> 5, cc = rem & 31;
        int gh = rt * 7 - 1 + r, gw = cc - 1;
        float v = 0.f;
        if ((unsigned)gh < 28u && (unsigned)gw < 28u)
            v = xb[c * 784 + gh * 28 + gw];
        unsigned u = __float_as_uint(v);
        xsd[i] = ((unsigned long long)u << 32) | u;
    }
    __syncthreads();

    const unsigned long long mask = 0x7FFFFFFF7FFFFFFFULL;
    unsigned long long acc0 = 0ull, acc1 = 0ull, acc2 = 0ull, acc3 = 0ull;

    if (col < 28) {
        #pragma unroll 1
        for (int c = 0; c < 8; ++c) {
            const unsigned long long* xc = xsd + c * 288 + row * 32 + col;
            const ulonglong2* wk = (const ulonglong2*)(nws + c * 36);
            #pragma unroll
            for (int r = 0; r < 3; ++r) {
                #pragma unroll
                for (int q = 0; q < 3; ++q) {
                    unsigned long long xx = xc[r * 32 + q];
                    ulonglong2 wA = wk[(r * 3 + q) * 2];
                    ulonglong2 wB = wk[(r * 3 + q) * 2 + 1];
                    adder2(acc0, xx, wA.x, mask);
                    adder2(acc1, xx, wA.y, mask);
                    adder2(acc2, xx, wB.x, mask);
                    adder2(acc3, xx, wB.y, mask);
                }
            }
        }

        const int gh = rt * 7 + row;
        const int hw = gh * 28 + col;
        float* pb = g_partial + ((size_t)(ks * 512 + n * 64 + ocg * 8)) * 784 + hw;
        unsigned long long a[4] = {acc0, acc1, acc2, acc3};
        #pragma unroll
        for (int p = 0; p < 4; ++p) {
            pb[(2 * p) * 784]     = __uint_as_float((unsigned)(a[p] & 0xFFFFFFFFu));
            pb[(2 * p + 1) * 784] = __uint_as_float((unsigned)(a[p] >> 32));
        }
    }
}

// Fused tail: combine + stats + global barrier + normalize. 512 blocks x 256.
__global__ __launch_bounds__(256) void tail_kernel(
    float* __restrict__ out, const float* __restrict__ gamma, const float* __restrict__ beta)
{
    __shared__ float rs[256], rq[256];
    __shared__ float sc_s, bi_s;

    const int bid = blockIdx.x;          // n*64 + oc
    const int oc  = bid & 63;
    const int tid = threadIdx.x;

    float4 v = make_float4(0.f, 0.f, 0.f, 0.f);
    float s = 0.f, sq = 0.f;
    if (tid < 196) {
        const int off = tid * 4;
        float4 a = *(const float4*)(g_partial + ((size_t)(0 * 512 + bid)) * 784 + off);
        float4 b = *(const float4*)(g_partial + ((size_t)(1 * 512 + bid)) * 784 + off);
        float4 c = *(const float4*)(g_partial + ((size_t)(2 * 512 + bid)) * 784 + off);
        float4 d = *(const float4*)(g_partial + ((size_t)(3 * 512 + bid)) * 784 + off);
        v.x = -(a.x + b.x + c.x + d.x);
        v.y = -(a.y + b.y + c.y + d.y);
        v.z = -(a.z + b.z + c.z + d.z);
        v.w = -(a.w + b.w + c.w + d.w);
        s  = v.x + v.y + v.z + v.w;
        sq = v.x * v.x + v.y * v.y + v.z * v.z + v.w * v.w;
    }
    rs[tid] = s; rq[tid] = sq;
    __syncthreads();
    #pragma unroll
    for (int st = 128; st > 0; st >>= 1) {
        if (tid < st) { rs[tid] += rs[tid + st]; rq[tid] += rq[tid + st]; }
        __syncthreads();
    }

    // Publish this (n,oc) partial; arrive at the global barrier; spin.
    if (tid == 0) {
        g_psum[bid] = rs[0];
        g_psumsq[bid] = rq[0];
        __threadfence();
        atomicAdd(&g_ctr, 1u);
        while (*(volatile unsigned*)&g_ctr < 512u) __nanosleep(64);
        __threadfence();
    }
    __syncthreads();

    // Per-channel stats: 8 lanes gather the 8 batch partials for this oc.
    if (tid < 8) {
        float ss = *(volatile float*)&g_psum[tid * 64 + oc];
        float qq = *(volatile float*)&g_psumsq[tid * 64 + oc];
        #pragma unroll
        for (int d = 4; d > 0; d >>= 1) {
            ss += __shfl_down_sync(0xFFu, ss, d, 8);
            qq += __shfl_down_sync(0xFFu, qq, d, 8);
        }
        if (tid == 0) {
            float mean = ss * (1.f / 6272.f);
            float var  = qq * (1.f / 6272.f) - mean * mean;
            float sc = gamma[oc] * rsqrtf(var + 1e-5f);
            sc_s = sc;
            bi_s = beta[oc] - mean * sc;
        }
    }
    __syncthreads();

    if (tid < 196) {
        const float sc = sc_s, bi = bi_s;
        v.x = v.x * sc + bi;
        v.y = v.y * sc + bi;
        v.z = v.z * sc + bi;
        v.w = v.w * sc + bi;
        *(float4*)(out + (size_t)bid * 784 + tid * 4) = v;
    }
}

extern "C" void kernel_launch(void* const* d_in, const int* in_sizes, int n_in,
                              void* d_out, int out_size) {
    const float* x     = (const float*)d_in[0];  // [8,32,28,28]
    const float* W     = (const float*)d_in[1];  // [64,32,3,3]
    const float* gamma = (const float*)d_in[2];  // [64]
    const float* beta  = (const float*)d_in[3];  // [64]
    float* out = (float*)d_out;                  // [8,64,28,28]

    dim3 g1(4, 8, 32);
    adder_partial_kernel<<<g1, 224>>>(x, W);
    tail_kernel<<<512, 256>>>(out, gamma, beta);
}

// round 8
// speedup vs baseline: 1.3884x; 1.0012x over previous
#include <cuda_runtime.h>

// AdderConv + BatchNorm2d (training stats): x[8,32,28,28], W[64,32,3,3], pad=1.
// out[n,o,h,w] = -sum_k |x - w|, then per-channel BN (biased var, eps=1e-5).
//
// Kernel 0 (pad): write x into zero-haloed, (x,x)-duplicated u64 scratch
//   g_xpad[n][c][30][32]. Conv then needs no halo logic and no x smem.
// Kernel 1 (conv partials): grid (4 row-tiles 7x28, 8 oc-groups, 8n x 4 ks)
//   = 1024 blocks x 224 thr, regs capped via __launch_bounds__(224,7).
//   Per k-iter: LDG.64 x (L1-hot) + 2x LDS.128 w (broadcast) +
//   4x (FADD2, 2xLOP3, FADD2). Positive partials -> g_partial.
// Kernel 2 (fused tail): 512 blocks x 256 thr; combine 4 partials in regs,
//   block-reduce sum/sumsq, software global barrier, scale/bias, normalize.

__device__ __align__(16) unsigned long long g_xpad[8 * 32 * 30 * 32];  // ~2MB
__device__ float g_partial[4 * 512 * 784];   // [ks][n*64+oc][hw], 6.4MB
__device__ float g_psum[512];
__device__ float g_psumsq[512];
__device__ unsigned g_ctr;

__device__ __forceinline__ void adder2(unsigned long long& acc,
                                       unsigned long long xx,
                                       unsigned long long w,
                                       unsigned long long mask) {
    asm("{\n\t"
        ".reg .b64 t;\n\t"
        "add.rn.f32x2 t, %1, %2;\n\t"
        "and.b64 t, t, %3;\n\t"
        "add.rn.f32x2 %0, %0, t;\n\t"
        "}"
        : "+l"(acc) : "l"(xx), "l"(w), "l"(mask));
}

// Kernel 0: build padded duplicated x. 240 blocks x 256 thr, 4 u64 each.
__global__ __launch_bounds__(256) void pad_kernel(const float* __restrict__ x)
{
    const int gid = blockIdx.x * 256 + threadIdx.x;       // 0..61439
    const int w0  = (gid * 4) & 31;
    const int rowid = gid >> 3;                            // 0..7679
    const int h  = rowid % 30;
    const int cn = rowid / 30;                             // n*32 + c
    unsigned long long* dst = g_xpad + ((size_t)cn * 30 + h) * 32 + w0;
    const float* src = x + ((size_t)cn * 28 + (h - 1)) * 28;
    #pragma unroll
    for (int j = 0; j < 4; ++j) {
        int w = w0 + j;
        float v = 0.f;
        if (h >= 1 && h <= 28 && w >= 1 && w <= 28) v = src[w - 1];
        unsigned u = __float_as_uint(v);
        dst[j] = ((unsigned long long)u << 32) | u;
    }
    if (gid == 0) g_ctr = 0;   // replay-safe reset for the tail barrier
}

__global__ __launch_bounds__(224, 7) void adder_partial_kernel(
    const float* __restrict__ W)
{
    __shared__ __align__(16) unsigned long long nws[72 * 4];   // 2.25KB

    const int rt  = blockIdx.x;          // row-tile 0..3 (rows rt*7 .. rt*7+6)
    const int ocg = blockIdx.y;          // 0..7
    const int zz  = blockIdx.z;          // 0..31
    const int ks  = zz & 3;
    const int n   = zz >> 2;
    const int tid = threadIdx.x;
    const int row = tid >> 5;            // warp id = output row in tile
    const int col = tid & 31;            // lanes 28..31 compute garbage, don't store

    // Negated W slice for this k-split, packed per oc-pair:
    // nws[lk*4+p] = pack(-W[2p][ks*72+lk], -W[2p+1][ks*72+lk])
    const float* Wb = W + (ocg * 8) * 288 + ks * 72;
    for (int i = tid; i < 72 * 4; i += 224) {
        int lk = i >> 2, p = i & 3;
        unsigned lo = __float_as_uint(-Wb[(2 * p) * 288 + lk]);
        unsigned hi = __float_as_uint(-Wb[(2 * p + 1) * 288 + lk]);
        nws[i] = ((unsigned long long)hi << 32) | lo;
    }
    __syncthreads();

    const unsigned long long mask = 0x7FFFFFFF7FFFFFFFULL;
    unsigned long long acc0 = 0ull, acc1 = 0ull, acc2 = 0ull, acc3 = 0ull;

    // x pointer: padded row h = rt*7+row+dr maps taps dr in 0..2; col+dq likewise.
    const unsigned long long* xp =
        g_xpad + (((size_t)(n * 32 + ks * 8) * 30) + rt * 7 + row) * 32 + col;

    #pragma unroll 1
    for (int c = 0; c < 8; ++c) {
        const ulonglong2* wk = (const ulonglong2*)(nws + c * 36);
        #pragma unroll
        for (int dr = 0; dr < 3; ++dr) {
            #pragma unroll
            for (int dq = 0; dq < 3; ++dq) {
                unsigned long long xx = xp[dr * 32 + dq];
                ulonglong2 wA = wk[(dr * 3 + dq) * 2];
                ulonglong2 wB = wk[(dr * 3 + dq) * 2 + 1];
                adder2(acc0, xx, wA.x, mask);
                adder2(acc1, xx, wA.y, mask);
                adder2(acc2, xx, wB.x, mask);
                adder2(acc3, xx, wB.y, mask);
            }
        }
        xp += 960;                       // next channel: 30*32 u64
    }

    if (col < 28) {
        const int gh = rt * 7 + row;
        const int hw = gh * 28 + col;
        float* pb = g_partial + ((size_t)(ks * 512 + n * 64 + ocg * 8)) * 784 + hw;
        unsigned long long a[4] = {acc0, acc1, acc2, acc3};
        #pragma unroll
        for (int p = 0; p < 4; ++p) {
            pb[(2 * p) * 784]     = __uint_as_float((unsigned)(a[p] & 0xFFFFFFFFu));
            pb[(2 * p + 1) * 784] = __uint_as_float((unsigned)(a[p] >> 32));
        }
    }
}

// Fused tail: combine + stats + global barrier + normalize. 512 blocks x 256.
__global__ __launch_bounds__(256) void tail_kernel(
    float* __restrict__ out, const float* __restrict__ gamma, const float* __restrict__ beta)
{
    __shared__ float rs[256], rq[256];
    __shared__ float sc_s, bi_s;

    const int bid = blockIdx.x;          // n*64 + oc
    const int oc  = bid & 63;
    const int tid = threadIdx.x;

    float4 v = make_float4(0.f, 0.f, 0.f, 0.f);
    float s = 0.f, sq = 0.f;
    if (tid < 196) {
        const int off = tid * 4;
        float4 a = *(const float4*)(g_partial + ((size_t)(0 * 512 + bid)) * 784 + off);
        float4 b = *(const float4*)(g_partial + ((size_t)(1 * 512 + bid)) * 784 + off);
        float4 c = *(const float4*)(g_partial + ((size_t)(2 * 512 + bid)) * 784 + off);
        float4 d = *(const float4*)(g_partial + ((size_t)(3 * 512 + bid)) * 784 + off);
        v.x = -(a.x + b.x + c.x + d.x);
        v.y = -(a.y + b.y + c.y + d.y);
        v.z = -(a.z + b.z + c.z + d.z);
        v.w = -(a.w + b.w + c.w + d.w);
        s  = v.x + v.y + v.z + v.w;
        sq = v.x * v.x + v.y * v.y + v.z * v.z + v.w * v.w;
    }
    rs[tid] = s; rq[tid] = sq;
    __syncthreads();
    #pragma unroll
    for (int st = 128; st > 0; st >>= 1) {
        if (tid < st) { rs[tid] += rs[tid + st]; rq[tid] += rq[tid + st]; }
        __syncthreads();
    }

    if (tid == 0) {
        g_psum[bid] = rs[0];
        g_psumsq[bid] = rq[0];
        __threadfence();
        atomicAdd(&g_ctr, 1u);
        while (*(volatile unsigned*)&g_ctr < 512u) __nanosleep(64);
        __threadfence();
    }
    __syncthreads();

    if (tid < 8) {
        float ss = *(volatile float*)&g_psum[tid * 64 + oc];
        float qq = *(volatile float*)&g_psumsq[tid * 64 + oc];
        #pragma unroll
        for (int d = 4; d > 0; d >>= 1) {
            ss += __shfl_down_sync(0xFFu, ss, d, 8);
            qq += __shfl_down_sync(0xFFu, qq, d, 8);
        }
        if (tid == 0) {
            float mean = ss * (1.f / 6272.f);
            float var  = qq * (1.f / 6272.f) - mean * mean;
            float sc = gamma[oc] * rsqrtf(var + 1e-5f);
            sc_s = sc;
            bi_s = beta[oc] - mean * sc;
        }
    }
    __syncthreads();

    if (tid < 196) {
        const float sc = sc_s, bi = bi_s;
        v.x = v.x * sc + bi;
        v.y = v.y * sc + bi;
        v.z = v.z * sc + bi;
        v.w = v.w * sc + bi;
        *(float4*)(out + (size_t)bid * 784 + tid * 4) = v;
    }
}

extern "C" void kernel_launch(void* const* d_in, const int* in_sizes, int n_in,
                              void* d_out, int out_size) {
    const float* x     = (const float*)d_in[0];  // [8,32,28,28]
    const float* W     = (const float*)d_in[1];  // [64,32,3,3]
    const float* gamma = (const float*)d_in[2];  // [64]
    const float* beta  = (const float*)d_in[3];  // [64]
    float* out = (float*)d_out;                  // [8,64,28,28]

    pad_kernel<<<240, 256>>>(x);
    dim3 g1(4, 8, 32);
    adder_partial_kernel<<<g1, 224>>>(W);
    tail_kernel<<<512, 256>>>(out, gamma, beta);
}